// round 3
// baseline (speedup 1.0000x reference)
#include <cuda_runtime.h>
#include <cstdint>
#include <math.h>

#define Hh 512
#define Wd 512
#define Cc 80
#define HW (Hh * Wd)
#define NBINS 1024
#define BINSHIFT 22
#define FLATBITS 25
#define FLATMASK ((1u << FLATBITS) - 1)
#define NBLOCKS 1280            /* 4 * 4 * 80 tiles of 128x128 */
#define CAND_CAP 16384
#define SH_CAND 4096

// ---- scratch (device globals; no runtime allocation) ----
__device__ unsigned int       g_hist[NBINS];
__device__ unsigned int       g_bmax[NBLOCKS];   // per-tile max raw key
__device__ unsigned long long g_cand[CAND_CAP];
__device__ unsigned int       g_ncand;
__device__ unsigned int       g_thrkey;

// monotonic float->uint key (total order matching float <)
__device__ __forceinline__ unsigned int fkey(float v) {
    unsigned int u = __float_as_uint(v);
    return (u & 0x80000000u) ? ~u : (u | 0x80000000u);
}
__device__ __forceinline__ float fkey_inv(unsigned int k) {
    unsigned int u = (k & 0x80000000u) ? (k ^ 0x80000000u) : ~k;
    return __uint_as_float(u);
}

// ---- K0: clear histogram ----
__global__ void clear_kernel() {
    g_hist[threadIdx.x] = 0u;
}

// ---- shared NMS row machinery (identical arithmetic in both passes) ----
struct RowCtx {
    const float* base;
    int x0, lane;
};

__device__ __forceinline__ void loadrow(const RowCtx& cx, int y, float4& h, float4& v) {
    const float NEG = __int_as_float(0xff800000);  // -inf
    if (y < 0 || y >= Hh) { h.x = h.y = h.z = h.w = NEG; v = h; return; }
    const float* q = cx.base + y * Wd;
    v = *(const float4*)(q + cx.lane * 4);
    float lft = __shfl_up_sync(0xffffffffu, v.w, 1);
    if (cx.lane == 0)  lft = (cx.x0 > 0) ? __ldg(q - 1) : NEG;
    float rgt = __shfl_down_sync(0xffffffffu, v.x, 1);
    if (cx.lane == 31) rgt = (cx.x0 + 128 < Wd) ? __ldg(q + 128) : NEG;
    h.x = fmaxf(fmaxf(lft,  v.x), v.y);
    h.y = fmaxf(fmaxf(v.x,  v.y), v.z);
    h.z = fmaxf(fmaxf(v.y,  v.z), v.w);
    h.w = fmaxf(fmaxf(v.z,  v.w), rgt);
}

// ---- K1: NMS + histogram + per-tile raw max (NO survivor list) ----
__global__ __launch_bounds__(256) void nms_hist_kernel(const float* __restrict__ hmap) {
    __shared__ unsigned int shist[NBINS];
    __shared__ unsigned int swmax[8];
    const int lane = threadIdx.x;
    const int tid = threadIdx.y * 32 + lane;
    for (int i = tid; i < NBINS; i += 256) shist[i] = 0u;
    __syncthreads();

    const int c  = blockIdx.z;
    const int x0 = blockIdx.x * 128;
    const int y0 = blockIdx.y * 128 + threadIdx.y * 16;
    RowCtx cx{hmap + (size_t)c * HW + x0, x0, lane};

    float4 h0, h1, h2, v1, v2, vd;
    loadrow(cx, y0 - 1, h0, vd);
    loadrow(cx, y0,     h1, v1);

    float tmax = __int_as_float(0xff800000);

#pragma unroll 4
    for (int r = 0; r < 16; r++) {
        loadrow(cx, y0 + r + 1, h2, v2);
        float m0 = fmaxf(fmaxf(h0.x, h1.x), h2.x);
        float m1 = fmaxf(fmaxf(h0.y, h1.y), h2.y);
        float m2 = fmaxf(fmaxf(h0.z, h1.z), h2.z);
        float m3 = fmaxf(fmaxf(h0.w, h1.w), h2.w);
        if (m0 == v1.x) atomicAdd(&shist[fkey(v1.x) >> BINSHIFT], 1u);
        if (m1 == v1.y) atomicAdd(&shist[fkey(v1.y) >> BINSHIFT], 1u);
        if (m2 == v1.z) atomicAdd(&shist[fkey(v1.z) >> BINSHIFT], 1u);
        if (m3 == v1.w) atomicAdd(&shist[fkey(v1.w) >> BINSHIFT], 1u);
        tmax = fmaxf(tmax, fmaxf(fmaxf(v1.x, v1.y), fmaxf(v1.z, v1.w)));
        h0 = h1; h1 = h2; v1 = v2;
    }

    // warp/block reduce the raw max
    unsigned int kmax = fkey(tmax);
    #pragma unroll
    for (int s = 16; s > 0; s >>= 1)
        kmax = max(kmax, __shfl_xor_sync(0xffffffffu, kmax, s));
    if (lane == 0) swmax[threadIdx.y] = kmax;
    __syncthreads();
    if (tid == 0) {
        unsigned int bm = swmax[0];
        #pragma unroll
        for (int i = 1; i < 8; i++) bm = max(bm, swmax[i]);
        unsigned int bid = ((unsigned)blockIdx.z * gridDim.y + blockIdx.y) * gridDim.x
                           + blockIdx.x;
        g_bmax[bid] = bm;
    }
    for (int i = tid; i < NBINS; i += 256) {
        unsigned int s = shist[i];
        if (s) atomicAdd(&g_hist[i], s);
    }
}

// ---- K2: threshold from histogram (1 block) ----
__global__ void thresh_kernel(int K) {
    __shared__ unsigned int s[NBINS];
    int t = threadIdx.x;
    s[t] = g_hist[t];
    __syncthreads();
    if (t == 0) {
        unsigned int cum = 0;
        int idx = 0;
        for (int i = NBINS - 1; i >= 0; i--) {
            cum += s[i];
            if (cum >= (unsigned int)K) { idx = i; break; }
        }
        g_thrkey = (unsigned int)idx << BINSHIFT;
        g_ncand = 0u;
    }
}

// ---- K3: re-run NMS only on tiles whose raw max clears the threshold ----
__global__ __launch_bounds__(256) void cand_kernel(const float* __restrict__ hmap) {
    unsigned int bid = ((unsigned)blockIdx.z * gridDim.y + blockIdx.y) * gridDim.x
                       + blockIdx.x;
    unsigned int thr = g_thrkey;
    if (g_bmax[bid] < thr) return;   // uniform: whole block exits

    const int lane = threadIdx.x;
    const int c  = blockIdx.z;
    const int x0 = blockIdx.x * 128;
    const int y0 = blockIdx.y * 128 + threadIdx.y * 16;
    RowCtx cx{hmap + (size_t)c * HW + x0, x0, lane};

    float4 h0, h1, h2, v1, v2, vd;
    loadrow(cx, y0 - 1, h0, vd);
    loadrow(cx, y0,     h1, v1);

#pragma unroll 4
    for (int r = 0; r < 16; r++) {
        int y = y0 + r;
        loadrow(cx, y + 1, h2, v2);
        float m0 = fmaxf(fmaxf(h0.x, h1.x), h2.x);
        float m1 = fmaxf(fmaxf(h0.y, h1.y), h2.y);
        float m2 = fmaxf(fmaxf(h0.z, h1.z), h2.z);
        float m3 = fmaxf(fmaxf(h0.w, h1.w), h2.w);
        unsigned int fl = (unsigned)c * HW + (unsigned)y * Wd
                          + (unsigned)(x0 + lane * 4);
        float vv[4] = {v1.x, v1.y, v1.z, v1.w};
        float mm[4] = {m0, m1, m2, m3};
        #pragma unroll
        for (int e = 0; e < 4; e++) {
            if (mm[e] == vv[e]) {
                unsigned int key = fkey(vv[e]);
                if (key >= thr) {
                    unsigned int p = atomicAdd(&g_ncand, 1u);
                    if (p < CAND_CAP)
                        g_cand[p] = ((unsigned long long)key << FLATBITS)
                                    | (unsigned long long)(FLATMASK - (fl + e));
                }
            }
        }
        h0 = h1; h1 = h2; v1 = v2;
    }
}

// ---- K4: exact rank of each candidate; gather + write output (1 block) ----
__global__ void output_kernel(const float* __restrict__ regs,
                              const float* __restrict__ wh,
                              const float* __restrict__ rot,
                              float* __restrict__ out, int K) {
    __shared__ unsigned long long sk[SH_CAND];
    unsigned int n = min(g_ncand, (unsigned int)CAND_CAP);
    bool sh = (n <= (unsigned int)SH_CAND);
    if (sh)
        for (unsigned int i = threadIdx.x; i < n; i += blockDim.x)
            sk[i] = g_cand[i];
    __syncthreads();

    for (unsigned int i = threadIdx.x; i < n; i += blockDim.x) {
        unsigned long long ki = sh ? sk[i] : g_cand[i];
        int rank = 0;
        for (unsigned int j = 0; j < n; j++) {
            unsigned long long kj = sh ? sk[j] : g_cand[j];
            rank += (kj > ki) ? 1 : 0;
        }
        if (rank < K) {
            unsigned int key  = (unsigned int)(ki >> FLATBITS);
            unsigned int flat = FLATMASK - (unsigned int)(ki & FLATMASK);
            unsigned int c    = flat / HW;
            unsigned int idx  = flat - c * HW;
            float yf = (float)(idx >> 9);
            float xf = (float)(idx & 511u);
            float v = fkey_inv(key);
            float score = 1.0f / (1.0f + expf(-v));
            float* o = out + (size_t)rank * 7;
            o[0] = xf + __ldg(&regs[idx]);
            o[1] = yf + __ldg(&regs[HW + idx]);
            o[2] = __ldg(&wh[idx]);
            o[3] = __ldg(&wh[HW + idx]);
            o[4] = __ldg(&rot[idx]);
            o[5] = score;
            o[6] = (float)c;
        }
    }
}

extern "C" void kernel_launch(void* const* d_in, const int* in_sizes, int n_in,
                              void* d_out, int out_size) {
    const float* hmap = (const float*)d_in[0];
    const float* regs = (const float*)d_in[1];
    const float* wh   = (const float*)d_in[2];
    const float* rot  = (const float*)d_in[3];
    float* out = (float*)d_out;
    int K = out_size / 7;  // B=1; [B,K,7]

    clear_kernel<<<1, NBINS>>>();
    dim3 blk(32, 8, 1);
    dim3 grd(Wd / 128, Hh / 128, Cc);   // (4, 4, 80)
    nms_hist_kernel<<<grd, blk>>>(hmap);
    thresh_kernel<<<1, NBINS>>>(K);
    cand_kernel<<<grd, blk>>>(hmap);
    output_kernel<<<1, 1024>>>(regs, wh, rot, out, K);
}

// round 5
// speedup vs baseline: 1.2218x; 1.2218x over previous
#include <cuda_runtime.h>
#include <cstdint>
#include <math.h>

#define Hh 512
#define Wd 512
#define Cc 80
#define HW (Hh * Wd)
#define NBINS 1024
#define BINSHIFT 22
#define FLATBITS 25
#define FLATMASK ((1u << FLATBITS) - 1)
#define RPW 16                    /* rows per warp chunk */
#define NCHUNK (Cc * (Hh / RPW))  /* 2560 */
#define CAND_CAP 16384
#define SH_CAND 4096

// ---- scratch ----
__device__ unsigned int       g_hist[NBINS];
__device__ unsigned int       g_cmax[NCHUNK];   // per-chunk max SURVIVOR key
__device__ unsigned long long g_cand[CAND_CAP];
__device__ unsigned int       g_ncand;
__device__ unsigned int       g_thrkey;

__device__ __forceinline__ unsigned int fkey(float v) {
    unsigned int u = __float_as_uint(v);
    return (u & 0x80000000u) ? ~u : (u | 0x80000000u);
}
__device__ __forceinline__ float fkey_inv(unsigned int k) {
    unsigned int u = (k & 0x80000000u) ? (k ^ 0x80000000u) : ~k;
    return __uint_as_float(u);
}

#define NEGF (-__builtin_huge_valf())

// Load one full 512-wide row (warp-collective, 16 cols/lane) and produce
// per-element horizontal 3-max. Identical arithmetic in both passes.
__device__ __forceinline__ void row_hv(const float* __restrict__ row, int lane,
                                       float* __restrict__ v, float* __restrict__ h) {
    const float4 a = *(const float4*)(row + lane * 16 + 0);
    const float4 b = *(const float4*)(row + lane * 16 + 4);
    const float4 c = *(const float4*)(row + lane * 16 + 8);
    const float4 d = *(const float4*)(row + lane * 16 + 12);
    v[0] = a.x; v[1] = a.y; v[2]  = a.z; v[3]  = a.w;
    v[4] = b.x; v[5] = b.y; v[6]  = b.z; v[7]  = b.w;
    v[8] = c.x; v[9] = c.y; v[10] = c.z; v[11] = c.w;
    v[12] = d.x; v[13] = d.y; v[14] = d.z; v[15] = d.w;
    float lft = __shfl_up_sync(0xffffffffu, v[15], 1);
    float rgt = __shfl_down_sync(0xffffffffu, v[0], 1);
    if (lane == 0)  lft = NEGF;
    if (lane == 31) rgt = NEGF;
    float p[15];
    #pragma unroll
    for (int i = 0; i < 15; i++) p[i] = fmaxf(v[i], v[i + 1]);
    h[0] = fmaxf(lft, p[0]);
    #pragma unroll
    for (int i = 1; i < 15; i++) h[i] = fmaxf(p[i - 1], v[i + 1]);
    h[15] = fmaxf(p[14], rgt);
}

__device__ __forceinline__ void row_neg(float* __restrict__ h) {
    #pragma unroll
    for (int i = 0; i < 16; i++) h[i] = NEGF;
}

// ---- K0: clear ----
__global__ void clear_kernel() { g_hist[threadIdx.x] = 0u; }

// ---- K1: full NMS scan, histogram of survivor keys, per-chunk survivor max ----
__global__ __launch_bounds__(128) void nms_hist_kernel(const float* __restrict__ hmap) {
    __shared__ unsigned int shist[NBINS];
    const int lane = threadIdx.x, w = threadIdx.y;
    const int tid = w * 32 + lane;
    for (int i = tid; i < NBINS; i += 128) shist[i] = 0u;
    __syncthreads();

    const int c  = blockIdx.y;
    const int y0 = blockIdx.x * (4 * RPW) + w * RPW;
    const float* __restrict__ base = hmap + (size_t)c * HW;

    float v[2][16], h[3][16];
    if (y0 > 0) row_hv(base + (y0 - 1) * Wd, lane, v[1], h[2]);
    else        row_neg(h[2]);
    row_hv(base + y0 * Wd, lane, v[0], h[0]);

    float smax = NEGF;
    #pragma unroll
    for (int r = 0; r < RPW; r++) {
        const int yn = y0 + r + 1;
        if (yn < Hh) row_hv(base + yn * Wd, lane, v[(r + 1) & 1], h[(r + 1) % 3]);
        else         row_neg(h[(r + 1) % 3]);
        #pragma unroll
        for (int i = 0; i < 16; i++) {
            float m = fmaxf(fmaxf(h[(r + 2) % 3][i], h[r % 3][i]), h[(r + 1) % 3][i]);
            float val = v[r & 1][i];
            if (m == val) {
                atomicAdd(&shist[fkey(val) >> BINSHIFT], 1u);
                smax = fmaxf(smax, val);
            }
        }
    }

    unsigned int km = fkey(smax);
    #pragma unroll
    for (int s = 16; s > 0; s >>= 1)
        km = max(km, __shfl_xor_sync(0xffffffffu, km, s));
    if (lane == 0)
        g_cmax[c * (Hh / RPW) + blockIdx.x * 4 + w] = km;

    __syncthreads();
    for (int i = tid; i < NBINS; i += 128) {
        unsigned int s = shist[i];
        if (s) atomicAdd(&g_hist[i], s);
    }
}

// ---- K2: threshold from histogram (1 block) ----
__global__ void thresh_kernel(int K) {
    __shared__ unsigned int s[NBINS];
    int t = threadIdx.x;
    s[t] = g_hist[t];
    __syncthreads();
    if (t == 0) {
        unsigned int cum = 0;
        int idx = 0;
        for (int i = NBINS - 1; i >= 0; i--) {
            cum += s[i];
            if (cum >= (unsigned int)K) { idx = i; break; }
        }
        g_thrkey = (unsigned int)idx << BINSHIFT;
        g_ncand = 0u;
    }
}

// ---- K3: re-run NMS only on chunks whose SURVIVOR max clears the threshold ----
__global__ __launch_bounds__(32) void cand_kernel(const float* __restrict__ hmap) {
    const unsigned int chunk = blockIdx.x;
    const unsigned int thr = g_thrkey;
    if (g_cmax[chunk] < thr) return;

    const int lane = threadIdx.x;
    const int c  = chunk / (Hh / RPW);
    const int y0 = (chunk % (Hh / RPW)) * RPW;
    const float* __restrict__ base = hmap + (size_t)c * HW;

    float v[2][16], h[3][16];
    if (y0 > 0) row_hv(base + (y0 - 1) * Wd, lane, v[1], h[2]);
    else        row_neg(h[2]);
    row_hv(base + y0 * Wd, lane, v[0], h[0]);

    #pragma unroll
    for (int r = 0; r < RPW; r++) {
        const int yn = y0 + r + 1;
        if (yn < Hh) row_hv(base + yn * Wd, lane, v[(r + 1) & 1], h[(r + 1) % 3]);
        else         row_neg(h[(r + 1) % 3]);
        #pragma unroll
        for (int i = 0; i < 16; i++) {
            float m = fmaxf(fmaxf(h[(r + 2) % 3][i], h[r % 3][i]), h[(r + 1) % 3][i]);
            float val = v[r & 1][i];
            if (m == val) {
                unsigned int key = fkey(val);
                if (key >= thr) {
                    unsigned int fl = (unsigned int)c * HW
                                    + (unsigned int)(y0 + r) * Wd
                                    + (unsigned int)(lane * 16 + i);
                    unsigned int p = atomicAdd(&g_ncand, 1u);
                    if (p < CAND_CAP)
                        g_cand[p] = ((unsigned long long)key << FLATBITS)
                                  | (unsigned long long)(FLATMASK - fl);
                }
            }
        }
    }
}

// ---- K4: exact rank; gather + write output (1 block) ----
__global__ void output_kernel(const float* __restrict__ regs,
                              const float* __restrict__ wh,
                              const float* __restrict__ rot,
                              float* __restrict__ out, int K) {
    __shared__ unsigned long long sk[SH_CAND];
    unsigned int n = min(g_ncand, (unsigned int)CAND_CAP);
    bool sh = (n <= (unsigned int)SH_CAND);
    if (sh)
        for (unsigned int i = threadIdx.x; i < n; i += blockDim.x)
            sk[i] = g_cand[i];
    __syncthreads();

    for (unsigned int i = threadIdx.x; i < n; i += blockDim.x) {
        unsigned long long ki = sh ? sk[i] : g_cand[i];
        int rank = 0;
        for (unsigned int j = 0; j < n; j++) {
            unsigned long long kj = sh ? sk[j] : g_cand[j];
            rank += (kj > ki) ? 1 : 0;
        }
        if (rank < K) {
            unsigned int key  = (unsigned int)(ki >> FLATBITS);
            unsigned int flat = FLATMASK - (unsigned int)(ki & FLATMASK);
            unsigned int c    = flat / HW;
            unsigned int idx  = flat - c * HW;
            float yf = (float)(idx >> 9);
            float xf = (float)(idx & 511u);
            float vv = fkey_inv(key);
            float score = 1.0f / (1.0f + expf(-vv));
            float* o = out + (size_t)rank * 7;
            o[0] = xf + __ldg(&regs[idx]);
            o[1] = yf + __ldg(&regs[HW + idx]);
            o[2] = __ldg(&wh[idx]);
            o[3] = __ldg(&wh[HW + idx]);
            o[4] = __ldg(&rot[idx]);
            o[5] = score;
            o[6] = (float)c;
        }
    }
}

extern "C" void kernel_launch(void* const* d_in, const int* in_sizes, int n_in,
                              void* d_out, int out_size) {
    const float* hmap = (const float*)d_in[0];
    const float* regs = (const float*)d_in[1];
    const float* wh   = (const float*)d_in[2];
    const float* rot  = (const float*)d_in[3];
    float* out = (float*)d_out;
    int K = out_size / 7;  // B=1; [B,K,7]

    clear_kernel<<<1, NBINS>>>();
    dim3 blk(32, 4, 1);
    dim3 grd(Hh / (4 * RPW), Cc, 1);   // (8, 80)
    nms_hist_kernel<<<grd, blk>>>(hmap);
    thresh_kernel<<<1, NBINS>>>(K);
    cand_kernel<<<NCHUNK, 32>>>(hmap);
    output_kernel<<<1, 1024>>>(regs, wh, rot, out, K);
}

// round 6
// speedup vs baseline: 1.5463x; 1.2655x over previous
#include <cuda_runtime.h>
#include <cstdint>
#include <math.h>

#define Hh 512
#define Wd 512
#define Cc 80
#define HW (Hh * Wd)
#define NBINS 1024
#define BINSHIFT 22
#define FLATBITS 25
#define FLATMASK ((1u << FLATBITS) - 1)
#define TROWS 16
#define NROWS (Cc * Hh)          /* 40960 per-row gates */
#define CAND_CAP 16384
#define SH_CAND 4096
#define NEGF (-__builtin_huge_valf())

// ---- scratch ----
__device__ unsigned int       g_hist[NBINS];
__device__ unsigned int       g_rmax[NROWS];   // per-row max SURVIVOR key
__device__ unsigned long long g_cand[CAND_CAP];
__device__ unsigned int       g_ncand;
__device__ unsigned int       g_thrkey;

__device__ __forceinline__ unsigned int fkey(float v) {
    unsigned int u = __float_as_uint(v);
    return (u & 0x80000000u) ? ~u : (u | 0x80000000u);
}
__device__ __forceinline__ float fkey_inv(unsigned int k) {
    unsigned int u = (k & 0x80000000u) ? (k ^ 0x80000000u) : ~k;
    return __uint_as_float(u);
}

// One full 512-wide row: lane holds 4 float4 groups at cols g*128 + lane*4.
// Produces per-element horizontal 3-max. IDENTICAL arithmetic in both passes.
__device__ __forceinline__ void row_hv4(const float* __restrict__ row, int lane,
                                        float4* __restrict__ v,
                                        float4* __restrict__ h) {
    #pragma unroll
    for (int g = 0; g < 4; g++)
        v[g] = *(const float4*)(row + g * 128 + lane * 4);
    #pragma unroll
    for (int g = 0; g < 4; g++) {
        float lft = __shfl_up_sync(0xffffffffu, v[g].w, 1);
        float rgt = __shfl_down_sync(0xffffffffu, v[g].x, 1);
        if (lane == 0)  lft = (g > 0) ? row[g * 128 - 1] : NEGF;
        if (lane == 31) rgt = (g < 3) ? row[g * 128 + 128] : NEGF;
        h[g].x = fmaxf(fmaxf(lft, v[g].x), v[g].y);
        h[g].y = fmaxf(fmaxf(v[g].x, v[g].y), v[g].z);
        h[g].z = fmaxf(fmaxf(v[g].y, v[g].z), v[g].w);
        h[g].w = fmaxf(fmaxf(v[g].z, v[g].w), rgt);
    }
}
__device__ __forceinline__ void row_neg4(float4* __restrict__ h) {
    #pragma unroll
    for (int g = 0; g < 4; g++) { h[g].x = h[g].y = h[g].z = h[g].w = NEGF; }
}

// ---- K0: clear ----
__global__ void clear_kernel() { g_hist[threadIdx.x] = 0u; }

// ---- K1: smem-staged NMS + histogram + per-row survivor max ----
__global__ __launch_bounds__(128, 4)
void nms_hist_kernel(const float* __restrict__ hmap) {
    __shared__ float stile[(TROWS + 2) * Wd];   // 36 KB, rows Y0-1..Y0+16
    __shared__ unsigned int shist[NBINS];
    const int tid = threadIdx.x;
    const int lane = tid & 31, w = tid >> 5;
    for (int i = tid; i < NBINS; i += 128) shist[i] = 0u;

    const int c  = blockIdx.y;
    const int Y0 = blockIdx.x * TROWS;
    const float* __restrict__ gb = hmap + (size_t)c * HW;

    // bulk load tile (+halo rows as -inf at image edges); deep MLP
    const float4 NEG4 = make_float4(NEGF, NEGF, NEGF, NEGF);
    #pragma unroll
    for (int i = tid; i < (TROWS + 2) * 128; i += 128) {
        int r = i >> 7, c4 = i & 127;
        int yg = Y0 - 1 + r;
        float4 val = (yg >= 0 && yg < Hh)
                   ? *(const float4*)(gb + (size_t)yg * Wd + c4 * 4) : NEG4;
        *(float4*)(stile + r * Wd + c4 * 4) = val;
    }
    __syncthreads();

    // each warp: 4 output rows, ring over h-rows
    float4 vb[2][4], hb[3][4];
    const int l0 = 4 * w;                 // tile-local index of row above first
    row_hv4(stile + l0 * Wd,       lane, vb[1], hb[2]);   // prev (v scratch)
    row_hv4(stile + (l0 + 1) * Wd, lane, vb[0], hb[0]);   // cur

    #pragma unroll
    for (int r = 0; r < 4; r++) {
        row_hv4(stile + (l0 + 2 + r) * Wd, lane, vb[(r + 1) & 1], hb[(r + 1) % 3]);
        const float4* P = hb[(r + 2) % 3];
        const float4* Cu = hb[r % 3];
        const float4* N = hb[(r + 1) % 3];
        const float4* V = vb[r & 1];
        float smax = NEGF;
        #pragma unroll
        for (int g = 0; g < 4; g++) {
            float m;
            m = fmaxf(fmaxf(P[g].x, Cu[g].x), N[g].x);
            if (m == V[g].x) { atomicAdd(&shist[fkey(V[g].x) >> BINSHIFT], 1u); smax = fmaxf(smax, V[g].x); }
            m = fmaxf(fmaxf(P[g].y, Cu[g].y), N[g].y);
            if (m == V[g].y) { atomicAdd(&shist[fkey(V[g].y) >> BINSHIFT], 1u); smax = fmaxf(smax, V[g].y); }
            m = fmaxf(fmaxf(P[g].z, Cu[g].z), N[g].z);
            if (m == V[g].z) { atomicAdd(&shist[fkey(V[g].z) >> BINSHIFT], 1u); smax = fmaxf(smax, V[g].z); }
            m = fmaxf(fmaxf(P[g].w, Cu[g].w), N[g].w);
            if (m == V[g].w) { atomicAdd(&shist[fkey(V[g].w) >> BINSHIFT], 1u); smax = fmaxf(smax, V[g].w); }
        }
        unsigned int km = fkey(smax);
        #pragma unroll
        for (int s = 16; s > 0; s >>= 1)
            km = max(km, __shfl_xor_sync(0xffffffffu, km, s));
        if (lane == 0) g_rmax[c * Hh + Y0 + 4 * w + r] = km;
    }

    __syncthreads();
    for (int i = tid; i < NBINS; i += 128) {
        unsigned int s = shist[i];
        if (s) atomicAdd(&g_hist[i], s);
    }
}

// ---- K2: threshold from histogram (1 block) ----
__global__ void thresh_kernel(int K) {
    __shared__ unsigned int s[NBINS];
    int t = threadIdx.x;
    s[t] = g_hist[t];
    __syncthreads();
    if (t == 0) {
        unsigned int cum = 0;
        int idx = 0;
        for (int i = NBINS - 1; i >= 0; i--) {
            cum += s[i];
            if (cum >= (unsigned int)K) { idx = i; break; }
        }
        g_thrkey = (unsigned int)idx << BINSHIFT;
        g_ncand = 0u;
    }
}

// ---- K3: rescan ONLY rows whose survivor max clears the threshold ----
__global__ __launch_bounds__(256) void cand_kernel(const float* __restrict__ hmap) {
    const int lane = threadIdx.x & 31;
    const unsigned int row = blockIdx.x * 8 + (threadIdx.x >> 5);
    const unsigned int thr = g_thrkey;
    if (g_rmax[row] < thr) return;   // warp-uniform

    const int c = row >> 9;
    const int y = row & 511;
    const float* __restrict__ base = hmap + (size_t)c * HW;

    float4 vP[4], vC[4], vN[4], hP[4], hC[4], hN[4];
    if (y > 0) row_hv4(base + (size_t)(y - 1) * Wd, lane, vP, hP);
    else       row_neg4(hP);
    row_hv4(base + (size_t)y * Wd, lane, vC, hC);
    if (y < Hh - 1) row_hv4(base + (size_t)(y + 1) * Wd, lane, vN, hN);
    else            row_neg4(hN);

    #pragma unroll
    for (int g = 0; g < 4; g++) {
        float vv[4] = {vC[g].x, vC[g].y, vC[g].z, vC[g].w};
        float mm[4] = {fmaxf(fmaxf(hP[g].x, hC[g].x), hN[g].x),
                       fmaxf(fmaxf(hP[g].y, hC[g].y), hN[g].y),
                       fmaxf(fmaxf(hP[g].z, hC[g].z), hN[g].z),
                       fmaxf(fmaxf(hP[g].w, hC[g].w), hN[g].w)};
        #pragma unroll
        for (int e = 0; e < 4; e++) {
            if (mm[e] == vv[e]) {
                unsigned int key = fkey(vv[e]);
                if (key >= thr) {
                    unsigned int fl = (unsigned int)c * HW + (unsigned int)y * Wd
                                    + (unsigned int)(g * 128 + lane * 4 + e);
                    unsigned int p = atomicAdd(&g_ncand, 1u);
                    if (p < CAND_CAP)
                        g_cand[p] = ((unsigned long long)key << FLATBITS)
                                  | (unsigned long long)(FLATMASK - fl);
                }
            }
        }
    }
}

// ---- K4: exact rank; gather + write output (1 block) ----
__global__ void output_kernel(const float* __restrict__ regs,
                              const float* __restrict__ wh,
                              const float* __restrict__ rot,
                              float* __restrict__ out, int K) {
    __shared__ unsigned long long sk[SH_CAND];
    unsigned int n = min(g_ncand, (unsigned int)CAND_CAP);
    bool sh = (n <= (unsigned int)SH_CAND);
    if (sh)
        for (unsigned int i = threadIdx.x; i < n; i += blockDim.x)
            sk[i] = g_cand[i];
    __syncthreads();

    for (unsigned int i = threadIdx.x; i < n; i += blockDim.x) {
        unsigned long long ki = sh ? sk[i] : g_cand[i];
        int rank = 0;
        for (unsigned int j = 0; j < n; j++) {
            unsigned long long kj = sh ? sk[j] : g_cand[j];
            rank += (kj > ki) ? 1 : 0;
        }
        if (rank < K) {
            unsigned int key  = (unsigned int)(ki >> FLATBITS);
            unsigned int flat = FLATMASK - (unsigned int)(ki & FLATMASK);
            unsigned int c    = flat / HW;
            unsigned int idx  = flat - c * HW;
            float yf = (float)(idx >> 9);
            float xf = (float)(idx & 511u);
            float vv = fkey_inv(key);
            float score = 1.0f / (1.0f + expf(-vv));
            float* o = out + (size_t)rank * 7;
            o[0] = xf + __ldg(&regs[idx]);
            o[1] = yf + __ldg(&regs[HW + idx]);
            o[2] = __ldg(&wh[idx]);
            o[3] = __ldg(&wh[HW + idx]);
            o[4] = __ldg(&rot[idx]);
            o[5] = score;
            o[6] = (float)c;
        }
    }
}

extern "C" void kernel_launch(void* const* d_in, const int* in_sizes, int n_in,
                              void* d_out, int out_size) {
    const float* hmap = (const float*)d_in[0];
    const float* regs = (const float*)d_in[1];
    const float* wh   = (const float*)d_in[2];
    const float* rot  = (const float*)d_in[3];
    float* out = (float*)d_out;
    int K = out_size / 7;  // B=1; [B,K,7]

    clear_kernel<<<1, NBINS>>>();
    nms_hist_kernel<<<dim3(Hh / TROWS, Cc), 128>>>(hmap);   // (32, 80)
    thresh_kernel<<<1, NBINS>>>(K);
    cand_kernel<<<NROWS / 8, 256>>>(hmap);
    output_kernel<<<1, 1024>>>(regs, wh, rot, out, K);
}

// round 7
// speedup vs baseline: 1.5780x; 1.0205x over previous
#include <cuda_runtime.h>
#include <cstdint>
#include <math.h>

#define Hh 512
#define Wd 512
#define Cc 80
#define HW (Hh * Wd)
#define NBINS 1024
#define BINSHIFT 22
#define FLATBITS 25
#define FLATMASK ((1u << FLATBITS) - 1)
#define TROWS 16
#define NROWS (Cc * Hh)          /* 40960 per-row gates */
#define HOT_CAP 8192
#define CAND_CAP 16384
#define SH_CAND 4096
#define NEGF (-__builtin_huge_valf())

// ---- scratch ----
__device__ unsigned int       g_hist[NBINS];     // self-cleaned by thresh
__device__ unsigned int       g_rmax[NROWS];     // per-row max SURVIVOR key
__device__ unsigned int       g_hotrows[HOT_CAP];
__device__ unsigned int       g_nhot;
__device__ unsigned long long g_cand[CAND_CAP];
__device__ unsigned int       g_ncand;
__device__ unsigned int       g_thrkey;

__device__ __forceinline__ unsigned int fkey(float v) {
    unsigned int u = __float_as_uint(v);
    return (u & 0x80000000u) ? ~u : (u | 0x80000000u);
}
__device__ __forceinline__ float fkey_inv(unsigned int k) {
    unsigned int u = (k & 0x80000000u) ? (k ^ 0x80000000u) : ~k;
    return __uint_as_float(u);
}

// One 128-col group of a 512-wide row: v = 4 elems/lane, h = horizontal 3-max.
// Works for shared or global row pointers; max-of-set is order-exact (no NaN),
// so pass 1 and pass 2 produce bit-identical predicates.
__device__ __forceinline__ void row_hv1(const float* __restrict__ row, int g,
                                        int lane, float4& v, float4& h) {
    v = *(const float4*)(row + g * 128 + lane * 4);
    float lft = __shfl_up_sync(0xffffffffu, v.w, 1);
    float rgt = __shfl_down_sync(0xffffffffu, v.x, 1);
    if (lane == 0)  lft = (g > 0) ? row[g * 128 - 1] : NEGF;
    if (lane == 31) rgt = (g < 3) ? row[g * 128 + 128] : NEGF;
    h.x = fmaxf(fmaxf(lft, v.x), v.y);
    h.y = fmaxf(fmaxf(v.x, v.y), v.z);
    h.z = fmaxf(fmaxf(v.y, v.z), v.w);
    h.w = fmaxf(fmaxf(v.z, v.w), rgt);
}

// ---- K1: smem-staged NMS + histogram + per-row survivor max ----
__global__ __launch_bounds__(256, 5)
void nms_hist_kernel(const float* __restrict__ hmap) {
    __shared__ float stile[(TROWS + 2) * Wd];   // 36 KB
    __shared__ unsigned int shist[NBINS];       // 4 KB
    __shared__ unsigned int srmax[TROWS];
    const int tid = threadIdx.x, lane = tid & 31, w = tid >> 5;
    for (int i = tid; i < NBINS; i += 256) shist[i] = 0u;
    if (tid < TROWS) srmax[tid] = 0u;

    const int c  = blockIdx.y;
    const int Y0 = blockIdx.x * TROWS;
    const float* __restrict__ gb = hmap + (size_t)c * HW;

    const float4 NEG4 = make_float4(NEGF, NEGF, NEGF, NEGF);
    #pragma unroll
    for (int k = 0; k < 9; k++) {
        int i = tid + k * 256;                 // 18 rows * 128 float4
        int r = i >> 7, c4 = i & 127;
        int yg = Y0 - 1 + r;
        float4 val = (yg >= 0 && yg < Hh)
                   ? *(const float4*)(gb + (size_t)yg * Wd + c4 * 4) : NEG4;
        *(float4*)(stile + r * Wd + c4 * 4) = val;
    }
    __syncthreads();

    // warp = (col-group g, 8-row half); small ring -> ~40 regs
    const int g  = w & 3;
    const int r0 = (w >> 2) * 8;               // content rows r0..r0+7
    float4 v[2], h[3];
    row_hv1(stile + r0 * Wd,       g, lane, v[1], h[2]);   // row above (v scratch)
    row_hv1(stile + (r0 + 1) * Wd, g, lane, v[0], h[0]);

    #pragma unroll
    for (int r = 0; r < 8; r++) {
        row_hv1(stile + (r0 + 2 + r) * Wd, g, lane, v[(r + 1) & 1], h[(r + 1) % 3]);
        float4 P = h[(r + 2) % 3], C = h[r % 3], N = h[(r + 1) % 3], V = v[r & 1];
        float smax = NEGF;
        float m;
        m = fmaxf(fmaxf(P.x, C.x), N.x);
        if (m == V.x) { atomicAdd(&shist[fkey(V.x) >> BINSHIFT], 1u); smax = fmaxf(smax, V.x); }
        m = fmaxf(fmaxf(P.y, C.y), N.y);
        if (m == V.y) { atomicAdd(&shist[fkey(V.y) >> BINSHIFT], 1u); smax = fmaxf(smax, V.y); }
        m = fmaxf(fmaxf(P.z, C.z), N.z);
        if (m == V.z) { atomicAdd(&shist[fkey(V.z) >> BINSHIFT], 1u); smax = fmaxf(smax, V.z); }
        m = fmaxf(fmaxf(P.w, C.w), N.w);
        if (m == V.w) { atomicAdd(&shist[fkey(V.w) >> BINSHIFT], 1u); smax = fmaxf(smax, V.w); }
        unsigned int km = fkey(smax);
        #pragma unroll
        for (int s = 16; s > 0; s >>= 1)
            km = max(km, __shfl_xor_sync(0xffffffffu, km, s));
        if (lane == 0) atomicMax(&srmax[r0 + r], km);
    }

    __syncthreads();
    if (tid < TROWS) g_rmax[c * Hh + Y0 + tid] = srmax[tid];
    for (int i = tid; i < NBINS; i += 256) {
        unsigned int s = shist[i];
        if (s) atomicAdd(&g_hist[i], s);
    }
}

// ---- K2: threshold (parallel suffix scan) + hot-row compaction + self-clean ----
__global__ void thresh_compact_kernel(int K) {
    __shared__ unsigned int s[NBINS];
    __shared__ unsigned int snhot;
    const int t = threadIdx.x;
    s[t] = g_hist[t];
    g_hist[t] = 0u;                       // self-clean for next graph replay
    if (t == 0) { snhot = 0u; g_ncand = 0u; g_thrkey = 0u; }
    __syncthreads();
    // Hillis-Steele suffix sum
    for (int d = 1; d < NBINS; d <<= 1) {
        unsigned int add = (t + d < NBINS) ? s[t + d] : 0u;
        __syncthreads();
        s[t] += add;
        __syncthreads();
    }
    if (s[t] >= (unsigned int)K && (t == NBINS - 1 || s[t + 1] < (unsigned int)K))
        g_thrkey = (unsigned int)t << BINSHIFT;
    __syncthreads();
    const unsigned int thr = g_thrkey;
    for (int r = t; r < NROWS; r += NBINS) {
        if (g_rmax[r] >= thr) {
            unsigned int p = atomicAdd(&snhot, 1u);
            if (p < HOT_CAP) g_hotrows[p] = (unsigned int)r;
        }
    }
    __syncthreads();
    if (t == 0) g_nhot = min(snhot, (unsigned int)HOT_CAP);
}

// ---- K3: rescan ONLY compacted hot rows (one warp per row) ----
__global__ __launch_bounds__(256) void cand_kernel(const float* __restrict__ hmap) {
    const unsigned int nhot = g_nhot;
    const unsigned int thr = g_thrkey;
    const int lane = threadIdx.x & 31;
    const unsigned int warps = gridDim.x * (blockDim.x >> 5);
    for (unsigned int wi = blockIdx.x * (blockDim.x >> 5) + (threadIdx.x >> 5);
         wi < nhot; wi += warps) {
        const unsigned int row = g_hotrows[wi];
        const int c = row >> 9;
        const int y = row & 511;
        const float* __restrict__ base = hmap + (size_t)c * HW;
        #pragma unroll
        for (int g = 0; g < 4; g++) {
            float4 vP, vC, vN, hP, hC, hN;
            if (y > 0) row_hv1(base + (size_t)(y - 1) * Wd, g, lane, vP, hP);
            else       { hP.x = hP.y = hP.z = hP.w = NEGF; }
            row_hv1(base + (size_t)y * Wd, g, lane, vC, hC);
            if (y < Hh - 1) row_hv1(base + (size_t)(y + 1) * Wd, g, lane, vN, hN);
            else            { hN.x = hN.y = hN.z = hN.w = NEGF; }
            float vv[4] = {vC.x, vC.y, vC.z, vC.w};
            float mm[4] = {fmaxf(fmaxf(hP.x, hC.x), hN.x),
                           fmaxf(fmaxf(hP.y, hC.y), hN.y),
                           fmaxf(fmaxf(hP.z, hC.z), hN.z),
                           fmaxf(fmaxf(hP.w, hC.w), hN.w)};
            #pragma unroll
            for (int e = 0; e < 4; e++) {
                if (mm[e] == vv[e]) {
                    unsigned int key = fkey(vv[e]);
                    if (key >= thr) {
                        unsigned int fl = (unsigned int)c * HW + (unsigned int)y * Wd
                                        + (unsigned int)(g * 128 + lane * 4 + e);
                        unsigned int p = atomicAdd(&g_ncand, 1u);
                        if (p < CAND_CAP)
                            g_cand[p] = ((unsigned long long)key << FLATBITS)
                                      | (unsigned long long)(FLATMASK - fl);
                    }
                }
            }
        }
    }
}

// ---- K4: exact rank; gather + write output (1 block) ----
__global__ void output_kernel(const float* __restrict__ regs,
                              const float* __restrict__ wh,
                              const float* __restrict__ rot,
                              float* __restrict__ out, int K) {
    __shared__ unsigned long long sk[SH_CAND];
    unsigned int n = min(g_ncand, (unsigned int)CAND_CAP);
    bool sh = (n <= (unsigned int)SH_CAND);
    if (sh)
        for (unsigned int i = threadIdx.x; i < n; i += blockDim.x)
            sk[i] = g_cand[i];
    __syncthreads();

    for (unsigned int i = threadIdx.x; i < n; i += blockDim.x) {
        unsigned long long ki = sh ? sk[i] : g_cand[i];
        int rank = 0;
        for (unsigned int j = 0; j < n; j++) {
            unsigned long long kj = sh ? sk[j] : g_cand[j];
            rank += (kj > ki) ? 1 : 0;
        }
        if (rank < K) {
            unsigned int key  = (unsigned int)(ki >> FLATBITS);
            unsigned int flat = FLATMASK - (unsigned int)(ki & FLATMASK);
            unsigned int c    = flat / HW;
            unsigned int idx  = flat - c * HW;
            float yf = (float)(idx >> 9);
            float xf = (float)(idx & 511u);
            float vv = fkey_inv(key);
            float score = 1.0f / (1.0f + expf(-vv));
            float* o = out + (size_t)rank * 7;
            o[0] = xf + __ldg(&regs[idx]);
            o[1] = yf + __ldg(&regs[HW + idx]);
            o[2] = __ldg(&wh[idx]);
            o[3] = __ldg(&wh[HW + idx]);
            o[4] = __ldg(&rot[idx]);
            o[5] = score;
            o[6] = (float)c;
        }
    }
}

extern "C" void kernel_launch(void* const* d_in, const int* in_sizes, int n_in,
                              void* d_out, int out_size) {
    const float* hmap = (const float*)d_in[0];
    const float* regs = (const float*)d_in[1];
    const float* wh   = (const float*)d_in[2];
    const float* rot  = (const float*)d_in[3];
    float* out = (float*)d_out;
    int K = out_size / 7;  // B=1; [B,K,7]

    nms_hist_kernel<<<dim3(Hh / TROWS, Cc), 256>>>(hmap);   // (32, 80)
    thresh_compact_kernel<<<1, NBINS>>>(K);
    cand_kernel<<<256, 256>>>(hmap);                        // 2048 warps, stride
    output_kernel<<<1, 1024>>>(regs, wh, rot, out, K);
}

// round 10
// speedup vs baseline: 2.2287x; 1.4124x over previous
#include <cuda_runtime.h>
#include <cstdint>
#include <math.h>

#define Hh 512
#define Wd 512
#define Cc 80
#define HW (Hh * Wd)
#define NBINS 1024
#define BINSHIFT 22
#define FLATBITS 25
#define FLATMASK ((1u << FLATBITS) - 1)
#define TROWS 16
#define NCHUNK (Cc * (Hh / 8) * 4)   /* 20480 gates: 8 rows x 128 cols */
#define HOT_CAP 8192
#define CAND_CAP 16384
#define SH_CAND 4096
#define NEGF (-__builtin_huge_valf())

// ---- scratch ----
__device__ unsigned int       g_hist[NBINS];     // self-cleaned by thresh
__device__ unsigned int       g_cmax[NCHUNK];    // per-chunk max SURVIVOR key
__device__ unsigned int       g_hot[HOT_CAP];
__device__ unsigned int       g_nhot;
__device__ unsigned long long g_cand[CAND_CAP];
__device__ unsigned int       g_ncand;
__device__ unsigned int       g_thrkey;

__device__ __forceinline__ unsigned int fkey(float v) {
    unsigned int u = __float_as_uint(v);
    return (u & 0x80000000u) ? ~u : (u | 0x80000000u);
}
__device__ __forceinline__ float fkey_inv(unsigned int k) {
    unsigned int u = (k & 0x80000000u) ? (k ^ 0x80000000u) : ~k;
    return __uint_as_float(u);
}

// One 128-col group of a 512-wide row: v = 4 elems/lane, h = horizontal 3-max.
// Same code path for shared or global rows; pure fmax-of-set (no NaN in data)
// so pass 1 and pass 2 produce bit-identical predicates.
__device__ __forceinline__ void row_hv1(const float* __restrict__ row, int g,
                                        int lane, float4& v, float4& h) {
    v = *(const float4*)(row + g * 128 + lane * 4);
    float lft = __shfl_up_sync(0xffffffffu, v.w, 1);
    float rgt = __shfl_down_sync(0xffffffffu, v.x, 1);
    if (lane == 0)  lft = (g > 0) ? row[g * 128 - 1] : NEGF;
    if (lane == 31) rgt = (g < 3) ? row[g * 128 + 128] : NEGF;
    h.x = fmaxf(fmaxf(lft, v.x), v.y);
    h.y = fmaxf(fmaxf(v.x, v.y), v.z);
    h.z = fmaxf(fmaxf(v.y, v.z), v.w);
    h.w = fmaxf(fmaxf(v.z, v.w), rgt);
}

// ---- K1: smem-staged NMS + histogram + per-chunk survivor max ----
__global__ __launch_bounds__(256, 5)
void nms_hist_kernel(const float* __restrict__ hmap) {
    __shared__ float stile[(TROWS + 2) * Wd];   // 36 KB
    __shared__ unsigned int shist[NBINS];       // 4 KB
    const int tid = threadIdx.x, lane = tid & 31, w = tid >> 5;
    for (int i = tid; i < NBINS; i += 256) shist[i] = 0u;

    const int c  = blockIdx.y;
    const int Y0 = blockIdx.x * TROWS;
    const float* __restrict__ gb = hmap + (size_t)c * HW;

    const float4 NEG4 = make_float4(NEGF, NEGF, NEGF, NEGF);
    #pragma unroll
    for (int k = 0; k < 9; k++) {
        int i = tid + k * 256;                 // 18 rows * 128 float4
        int r = i >> 7, c4 = i & 127;
        int yg = Y0 - 1 + r;
        float4 val = (yg >= 0 && yg < Hh)
                   ? *(const float4*)(gb + (size_t)yg * Wd + c4 * 4) : NEG4;
        *(float4*)(stile + r * Wd + c4 * 4) = val;
    }
    __syncthreads();

    // warp owns chunk (col-group g, 8-row half) exclusively
    const int g  = w & 3;
    const int half = w >> 2;
    const int r0 = half * 8;
    float4 v[2], h[3];
    row_hv1(stile + r0 * Wd,       g, lane, v[1], h[2]);
    row_hv1(stile + (r0 + 1) * Wd, g, lane, v[0], h[0]);

    float smax = NEGF;
    #pragma unroll
    for (int r = 0; r < 8; r++) {
        row_hv1(stile + (r0 + 2 + r) * Wd, g, lane, v[(r + 1) & 1], h[(r + 1) % 3]);
        float4 P = h[(r + 2) % 3], C = h[r % 3], N = h[(r + 1) % 3], V = v[r & 1];
        float m;
        m = fmaxf(fmaxf(P.x, C.x), N.x);
        if (m == V.x) { atomicAdd(&shist[fkey(V.x) >> BINSHIFT], 1u); smax = fmaxf(smax, V.x); }
        m = fmaxf(fmaxf(P.y, C.y), N.y);
        if (m == V.y) { atomicAdd(&shist[fkey(V.y) >> BINSHIFT], 1u); smax = fmaxf(smax, V.y); }
        m = fmaxf(fmaxf(P.z, C.z), N.z);
        if (m == V.z) { atomicAdd(&shist[fkey(V.z) >> BINSHIFT], 1u); smax = fmaxf(smax, V.z); }
        m = fmaxf(fmaxf(P.w, C.w), N.w);
        if (m == V.w) { atomicAdd(&shist[fkey(V.w) >> BINSHIFT], 1u); smax = fmaxf(smax, V.w); }
    }

    unsigned int km = fkey(smax);
    #pragma unroll
    for (int s = 16; s > 0; s >>= 1)
        km = max(km, __shfl_xor_sync(0xffffffffu, km, s));
    if (lane == 0) {
        unsigned int ych = (unsigned int)(Y0 >> 3) + half;
        g_cmax[((unsigned int)c * (Hh / 8) + ych) * 4 + g] = km;
    }

    __syncthreads();
    for (int i = tid; i < NBINS; i += 256) {
        unsigned int s = shist[i];
        if (s) atomicAdd(&g_hist[i], s);
    }
}

// ---- K2: threshold (parallel suffix scan, self-cleaning) ----
__global__ void thresh_kernel(int K) {
    __shared__ unsigned int s[NBINS];
    const int t = threadIdx.x;
    s[t] = g_hist[t];
    g_hist[t] = 0u;                       // clean for next graph replay
    if (t == 0) { g_nhot = 0u; g_ncand = 0u; g_thrkey = 0u; }
    __syncthreads();
    for (int d = 1; d < NBINS; d <<= 1) {
        unsigned int add = (t + d < NBINS) ? s[t + d] : 0u;
        __syncthreads();
        s[t] += add;
        __syncthreads();
    }
    if (s[t] >= (unsigned int)K && (t == NBINS - 1 || s[t + 1] < (unsigned int)K))
        g_thrkey = (unsigned int)t << BINSHIFT;
}

// ---- K2b: compact hot chunks (multi-block) ----
__global__ void compact_kernel() {
    const unsigned int thr = g_thrkey;
    unsigned int i = blockIdx.x * blockDim.x + threadIdx.x;
    if (i < NCHUNK && g_cmax[i] >= thr) {
        unsigned int p = atomicAdd(&g_nhot, 1u);
        if (p < HOT_CAP) g_hot[p] = i;
    }
}

// ---- K3: rescan ONLY hot chunks (one warp per chunk, grid-stride) ----
__global__ __launch_bounds__(256) void cand_kernel(const float* __restrict__ hmap) {
    const unsigned int nhot = min(g_nhot, (unsigned int)HOT_CAP);
    const unsigned int thr = g_thrkey;
    const int lane = threadIdx.x & 31;
    const unsigned int warps = gridDim.x * (blockDim.x >> 5);
    for (unsigned int wi = blockIdx.x * (blockDim.x >> 5) + (threadIdx.x >> 5);
         wi < nhot; wi += warps) {
        const unsigned int chunk = g_hot[wi];
        const int g   = chunk & 3;
        const int ych = (chunk >> 2) & 63;
        const int c   = chunk >> 8;
        const int y0  = ych * 8;
        const float* __restrict__ base = hmap + (size_t)c * HW;

        float4 v[2], h[3];
        if (y0 > 0) row_hv1(base + (size_t)(y0 - 1) * Wd, g, lane, v[1], h[2]);
        else        { h[2].x = h[2].y = h[2].z = h[2].w = NEGF; }
        row_hv1(base + (size_t)y0 * Wd, g, lane, v[0], h[0]);

        #pragma unroll
        for (int r = 0; r < 8; r++) {
            const int yn = y0 + r + 1;
            if (yn < Hh) row_hv1(base + (size_t)yn * Wd, g, lane,
                                 v[(r + 1) & 1], h[(r + 1) % 3]);
            else         { float4& hh = h[(r + 1) % 3];
                           hh.x = hh.y = hh.z = hh.w = NEGF; }
            float4 P = h[(r + 2) % 3], C = h[r % 3], N = h[(r + 1) % 3], V = v[r & 1];
            float vv[4] = {V.x, V.y, V.z, V.w};
            float mm[4] = {fmaxf(fmaxf(P.x, C.x), N.x),
                           fmaxf(fmaxf(P.y, C.y), N.y),
                           fmaxf(fmaxf(P.z, C.z), N.z),
                           fmaxf(fmaxf(P.w, C.w), N.w)};
            #pragma unroll
            for (int e = 0; e < 4; e++) {
                if (mm[e] == vv[e]) {
                    unsigned int key = fkey(vv[e]);
                    if (key >= thr) {
                        unsigned int fl = (unsigned int)c * HW
                                        + (unsigned int)(y0 + r) * Wd
                                        + (unsigned int)(g * 128 + lane * 4 + e);
                        unsigned int p = atomicAdd(&g_ncand, 1u);
                        if (p < CAND_CAP)
                            g_cand[p] = ((unsigned long long)key << FLATBITS)
                                      | (unsigned long long)(FLATMASK - fl);
                    }
                }
            }
        }
    }
}

// ---- K4: exact rank (multi-block); gather + write output ----
__global__ __launch_bounds__(256) void output_kernel(const float* __restrict__ regs,
                              const float* __restrict__ wh,
                              const float* __restrict__ rot,
                              float* __restrict__ out, int K) {
    __shared__ unsigned long long sk[SH_CAND];
    unsigned int n = min(g_ncand, (unsigned int)CAND_CAP);
    bool sh = (n <= (unsigned int)SH_CAND);
    if (sh)
        for (unsigned int i = threadIdx.x; i < n; i += blockDim.x)
            sk[i] = g_cand[i];
    __syncthreads();

    for (unsigned int i = blockIdx.x * blockDim.x + threadIdx.x; i < n;
         i += gridDim.x * blockDim.x) {
        unsigned long long ki = sh ? sk[i] : g_cand[i];
        int rank = 0;
        for (unsigned int j = 0; j < n; j++) {
            unsigned long long kj = sh ? sk[j] : g_cand[j];
            rank += (kj > ki) ? 1 : 0;
        }
        if (rank < K) {
            unsigned int key  = (unsigned int)(ki >> FLATBITS);
            unsigned int flat = FLATMASK - (unsigned int)(ki & FLATMASK);
            unsigned int c    = flat / HW;
            unsigned int idx  = flat - c * HW;
            float yf = (float)(idx >> 9);
            float xf = (float)(idx & 511u);
            float vv = fkey_inv(key);
            float score = 1.0f / (1.0f + expf(-vv));
            float* o = out + (size_t)rank * 7;
            o[0] = xf + __ldg(&regs[idx]);
            o[1] = yf + __ldg(&regs[HW + idx]);
            o[2] = __ldg(&wh[idx]);
            o[3] = __ldg(&wh[HW + idx]);
            o[4] = __ldg(&rot[idx]);
            o[5] = score;
            o[6] = (float)c;
        }
    }
}

extern "C" void kernel_launch(void* const* d_in, const int* in_sizes, int n_in,
                              void* d_out, int out_size) {
    const float* hmap = (const float*)d_in[0];
    const float* regs = (const float*)d_in[1];
    const float* wh   = (const float*)d_in[2];
    const float* rot  = (const float*)d_in[3];
    float* out = (float*)d_out;
    int K = out_size / 7;  // B=1; [B,K,7]

    nms_hist_kernel<<<dim3(Hh / TROWS, Cc), 256>>>(hmap);   // (32, 80)
    thresh_kernel<<<1, NBINS>>>(K);
    compact_kernel<<<NCHUNK / 256, 256>>>();
    cand_kernel<<<128, 256>>>(hmap);
    output_kernel<<<16, 256>>>(regs, wh, rot, out, K);
}

// round 12
// speedup vs baseline: 2.4155x; 1.0838x over previous
#include <cuda_runtime.h>
#include <cstdint>
#include <math.h>

#define Hh 512
#define Wd 512
#define Cc 80
#define HW (Hh * Wd)
#define NBINS 1024
#define BINSHIFT 22
#define FLATBITS 25
#define FLATMASK ((1u << FLATBITS) - 1)
#define TROWS 16
#define NCHUNK (Cc * (Hh / 8) * 4)   /* 20480 gates: 8 rows x 128 cols */
#define HOT_CAP 8192
#define CAND_CAP 16384
#define SH_CAND 4096
#define NEGF (-__builtin_huge_valf())

// ---- scratch ----
__device__ unsigned int       g_hist[NBINS];     // self-cleaned by thresh
__device__ unsigned int       g_cmax[NCHUNK];    // per-chunk max SURVIVOR key
__device__ unsigned int       g_hot[HOT_CAP];
__device__ unsigned int       g_nhot;
__device__ unsigned long long g_cand[CAND_CAP];
__device__ unsigned int       g_ncand;
__device__ unsigned int       g_thrkey;

__device__ __forceinline__ unsigned int fkey(float v) {
    unsigned int u = __float_as_uint(v);
    return (u & 0x80000000u) ? ~u : (u | 0x80000000u);
}
__device__ __forceinline__ float fkey_inv(unsigned int k) {
    unsigned int u = (k & 0x80000000u) ? (k ^ 0x80000000u) : ~k;
    return __uint_as_float(u);
}

// One 128-col group of a 512-wide row: v = 4 elems/lane, h = horizontal 3-max.
// Pure fmax-of-set (data NaN-free) -> identical predicates in both passes.
__device__ __forceinline__ void row_hv1(const float* __restrict__ row, int g,
                                        int lane, float4& v, float4& h) {
    v = *(const float4*)(row + g * 128 + lane * 4);
    float lft = __shfl_up_sync(0xffffffffu, v.w, 1);
    float rgt = __shfl_down_sync(0xffffffffu, v.x, 1);
    if (lane == 0)  lft = (g > 0) ? row[g * 128 - 1] : NEGF;
    if (lane == 31) rgt = (g < 3) ? row[g * 128 + 128] : NEGF;
    h.x = fmaxf(fmaxf(lft, v.x), v.y);
    h.y = fmaxf(fmaxf(v.x, v.y), v.z);
    h.z = fmaxf(fmaxf(v.y, v.z), v.w);
    h.w = fmaxf(fmaxf(v.z, v.w), rgt);
}

// h from already-loaded v + halo scalars; SAME fmax sequence as row_hv1.
__device__ __forceinline__ void hv_from_v(const float4& v, float hl, float hr,
                                          int g, int lane, float4& h) {
    float lft = __shfl_up_sync(0xffffffffu, v.w, 1);
    float rgt = __shfl_down_sync(0xffffffffu, v.x, 1);
    if (lane == 0)  lft = hl;
    if (lane == 31) rgt = hr;
    h.x = fmaxf(fmaxf(lft, v.x), v.y);
    h.y = fmaxf(fmaxf(v.x, v.y), v.z);
    h.z = fmaxf(fmaxf(v.y, v.z), v.w);
    h.w = fmaxf(fmaxf(v.z, v.w), rgt);
}

// ---- K1: smem-staged NMS + histogram + per-chunk survivor max ----
__global__ __launch_bounds__(256, 5)
void nms_hist_kernel(const float* __restrict__ hmap) {
    __shared__ float stile[(TROWS + 2) * Wd];   // 36 KB
    __shared__ unsigned int shist[NBINS];       // 4 KB
    const int tid = threadIdx.x, lane = tid & 31, w = tid >> 5;
    for (int i = tid; i < NBINS; i += 256) shist[i] = 0u;

    const int c  = blockIdx.y;
    const int Y0 = blockIdx.x * TROWS;
    const float* __restrict__ gb = hmap + (size_t)c * HW;

    const float4 NEG4 = make_float4(NEGF, NEGF, NEGF, NEGF);
    #pragma unroll
    for (int k = 0; k < 9; k++) {
        int i = tid + k * 256;                 // 18 rows * 128 float4
        int r = i >> 7, c4 = i & 127;
        int yg = Y0 - 1 + r;
        float4 val = (yg >= 0 && yg < Hh)
                   ? *(const float4*)(gb + (size_t)yg * Wd + c4 * 4) : NEG4;
        *(float4*)(stile + r * Wd + c4 * 4) = val;
    }
    __syncthreads();

    // warp owns chunk (col-group g, 8-row half) exclusively
    const int g  = w & 3;
    const int half = w >> 2;
    const int r0 = half * 8;
    float4 v[2], h[3];
    row_hv1(stile + r0 * Wd,       g, lane, v[1], h[2]);
    row_hv1(stile + (r0 + 1) * Wd, g, lane, v[0], h[0]);

    float smax = NEGF;
    #pragma unroll
    for (int r = 0; r < 8; r++) {
        row_hv1(stile + (r0 + 2 + r) * Wd, g, lane, v[(r + 1) & 1], h[(r + 1) % 3]);
        float4 P = h[(r + 2) % 3], C = h[r % 3], N = h[(r + 1) % 3], V = v[r & 1];
        float m;
        m = fmaxf(fmaxf(P.x, C.x), N.x);
        if (m == V.x) { atomicAdd(&shist[fkey(V.x) >> BINSHIFT], 1u); smax = fmaxf(smax, V.x); }
        m = fmaxf(fmaxf(P.y, C.y), N.y);
        if (m == V.y) { atomicAdd(&shist[fkey(V.y) >> BINSHIFT], 1u); smax = fmaxf(smax, V.y); }
        m = fmaxf(fmaxf(P.z, C.z), N.z);
        if (m == V.z) { atomicAdd(&shist[fkey(V.z) >> BINSHIFT], 1u); smax = fmaxf(smax, V.z); }
        m = fmaxf(fmaxf(P.w, C.w), N.w);
        if (m == V.w) { atomicAdd(&shist[fkey(V.w) >> BINSHIFT], 1u); smax = fmaxf(smax, V.w); }
    }

    unsigned int km = fkey(smax);
    #pragma unroll
    for (int s = 16; s > 0; s >>= 1)
        km = max(km, __shfl_xor_sync(0xffffffffu, km, s));
    if (lane == 0) {
        unsigned int ych = (unsigned int)(Y0 >> 3) + half;
        g_cmax[((unsigned int)c * (Hh / 8) + ych) * 4 + g] = km;
    }

    __syncthreads();
    for (int i = tid; i < NBINS; i += 256) {
        unsigned int s = shist[i];
        if (s) atomicAdd(&g_hist[i], s);
    }
}

// ---- K2: threshold (parallel suffix scan, self-cleaning) ----
__global__ void thresh_kernel(int K) {
    __shared__ unsigned int s[NBINS];
    const int t = threadIdx.x;
    s[t] = g_hist[t];
    g_hist[t] = 0u;                       // clean for next graph replay
    if (t == 0) { g_nhot = 0u; g_ncand = 0u; g_thrkey = 0u; }
    __syncthreads();
    for (int d = 1; d < NBINS; d <<= 1) {
        unsigned int add = (t + d < NBINS) ? s[t + d] : 0u;
        __syncthreads();
        s[t] += add;
        __syncthreads();
    }
    if (s[t] >= (unsigned int)K && (t == NBINS - 1 || s[t + 1] < (unsigned int)K))
        g_thrkey = (unsigned int)t << BINSHIFT;
}

// ---- K2b: compact hot chunks (multi-block) ----
__global__ void compact_kernel() {
    const unsigned int thr = g_thrkey;
    unsigned int i = blockIdx.x * blockDim.x + threadIdx.x;
    if (i < NCHUNK && g_cmax[i] >= thr) {
        unsigned int p = atomicAdd(&g_nhot, 1u);
        if (p < HOT_CAP) g_hot[p] = i;
    }
}

// ---- K3: rescan hot chunks; ALL 10 row loads issued up-front (MLP=10) ----
__global__ __launch_bounds__(128) void cand_kernel(const float* __restrict__ hmap) {
    const unsigned int nhot = min(g_nhot, (unsigned int)HOT_CAP);
    const unsigned int thr = g_thrkey;
    const int lane = threadIdx.x & 31;
    const unsigned int warps = gridDim.x * (blockDim.x >> 5);
    for (unsigned int wi = blockIdx.x * (blockDim.x >> 5) + (threadIdx.x >> 5);
         wi < nhot; wi += warps) {
        const unsigned int chunk = g_hot[wi];
        const int g   = chunk & 3;
        const int ych = (chunk >> 2) & 63;
        const int c   = chunk >> 8;
        const int y0  = ych * 8;
        const float* __restrict__ base = hmap + (size_t)c * HW;

        // ---- load phase: 10 independent rows ----
        float4 vr[10];
        float hl[10], hr[10];
        #pragma unroll
        for (int r = 0; r < 10; r++) {
            int yg = y0 - 1 + r;
            bool ok = (yg >= 0) && (yg < Hh);
            const float* row = base + (size_t)(ok ? yg : 0) * Wd;
            if (ok) {
                vr[r] = *(const float4*)(row + g * 128 + lane * 4);
                hl[r] = (lane == 0)  ? ((g > 0) ? row[g * 128 - 1]   : NEGF) : NEGF;
                hr[r] = (lane == 31) ? ((g < 3) ? row[g * 128 + 128] : NEGF) : NEGF;
            } else {
                vr[r].x = vr[r].y = vr[r].z = vr[r].w = NEGF;
                hl[r] = NEGF; hr[r] = NEGF;
            }
        }
        // ---- compute phase: identical fmax sequence to pass 1 ----
        float4 h[10];
        #pragma unroll
        for (int r = 0; r < 10; r++)
            hv_from_v(vr[r], hl[r], hr[r], g, lane, h[r]);

        #pragma unroll
        for (int r = 0; r < 8; r++) {
            float4 P = h[r], C = h[r + 1], N = h[r + 2], V = vr[r + 1];
            float vv[4] = {V.x, V.y, V.z, V.w};
            float mm[4] = {fmaxf(fmaxf(P.x, C.x), N.x),
                           fmaxf(fmaxf(P.y, C.y), N.y),
                           fmaxf(fmaxf(P.z, C.z), N.z),
                           fmaxf(fmaxf(P.w, C.w), N.w)};
            #pragma unroll
            for (int e = 0; e < 4; e++) {
                if (mm[e] == vv[e]) {
                    unsigned int key = fkey(vv[e]);
                    if (key >= thr) {
                        unsigned int fl = (unsigned int)c * HW
                                        + (unsigned int)(y0 + r) * Wd
                                        + (unsigned int)(g * 128 + lane * 4 + e);
                        unsigned int p = atomicAdd(&g_ncand, 1u);
                        if (p < CAND_CAP)
                            g_cand[p] = ((unsigned long long)key << FLATBITS)
                                      | (unsigned long long)(FLATMASK - fl);
                    }
                }
            }
        }
    }
}

// ---- K4: exact rank (multi-block); gather + write output ----
__global__ __launch_bounds__(256) void output_kernel(const float* __restrict__ regs,
                              const float* __restrict__ wh,
                              const float* __restrict__ rot,
                              float* __restrict__ out, int K) {
    __shared__ unsigned long long sk[SH_CAND];
    unsigned int n = min(g_ncand, (unsigned int)CAND_CAP);
    bool sh = (n <= (unsigned int)SH_CAND);
    if (sh)
        for (unsigned int i = threadIdx.x; i < n; i += blockDim.x)
            sk[i] = g_cand[i];
    __syncthreads();

    for (unsigned int i = blockIdx.x * blockDim.x + threadIdx.x; i < n;
         i += gridDim.x * blockDim.x) {
        unsigned long long ki = sh ? sk[i] : g_cand[i];
        int rank = 0;
        for (unsigned int j = 0; j < n; j++) {
            unsigned long long kj = sh ? sk[j] : g_cand[j];
            rank += (kj > ki) ? 1 : 0;
        }
        if (rank < K) {
            unsigned int key  = (unsigned int)(ki >> FLATBITS);
            unsigned int flat = FLATMASK - (unsigned int)(ki & FLATMASK);
            unsigned int c    = flat / HW;
            unsigned int idx  = flat - c * HW;
            float yf = (float)(idx >> 9);
            float xf = (float)(idx & 511u);
            float vv = fkey_inv(key);
            float score = 1.0f / (1.0f + expf(-vv));
            float* o = out + (size_t)rank * 7;
            o[0] = xf + __ldg(&regs[idx]);
            o[1] = yf + __ldg(&regs[HW + idx]);
            o[2] = __ldg(&wh[idx]);
            o[3] = __ldg(&wh[HW + idx]);
            o[4] = __ldg(&rot[idx]);
            o[5] = score;
            o[6] = (float)c;
        }
    }
}

extern "C" void kernel_launch(void* const* d_in, const int* in_sizes, int n_in,
                              void* d_out, int out_size) {
    const float* hmap = (const float*)d_in[0];
    const float* regs = (const float*)d_in[1];
    const float* wh   = (const float*)d_in[2];
    const float* rot  = (const float*)d_in[3];
    float* out = (float*)d_out;
    int K = out_size / 7;  // B=1; [B,K,7]

    nms_hist_kernel<<<dim3(Hh / TROWS, Cc), 256>>>(hmap);   // (32, 80)
    thresh_kernel<<<1, NBINS>>>(K);
    compact_kernel<<<NCHUNK / 256, 256>>>();
    cand_kernel<<<256, 128>>>(hmap);
    output_kernel<<<32, 256>>>(regs, wh, rot, out, K);
}

// round 14
// speedup vs baseline: 2.6710x; 1.1058x over previous
#include <cuda_runtime.h>
#include <cstdint>
#include <math.h>

#define Hh 512
#define Wd 512
#define Cc 80
#define HW (Hh * Wd)
#define NBINS 1024
#define BINSHIFT 22
#define FLATBITS 25
#define FLATMASK ((1u << FLATBITS) - 1)
#define NCHUNK (Cc * (Hh / 8) * 4)   /* 20480 gates: 8 rows x 128 cols */
#define HOT_CAP 8192
#define CAND_CAP 16384
#define SH_CAND 4096
#define NEGF (-__builtin_huge_valf())

// ---- scratch ----
__device__ unsigned int       g_hist[NBINS];     // self-cleaned by thresh
__device__ unsigned int       g_cmax[NCHUNK];    // per-chunk max SURVIVOR key
__device__ unsigned int       g_hot[HOT_CAP];
__device__ unsigned int       g_nhot;
__device__ unsigned long long g_cand[CAND_CAP];
__device__ unsigned int       g_ncand;
__device__ unsigned int       g_thrkey;

__device__ __forceinline__ unsigned int fkey(float v) {
    unsigned int u = __float_as_uint(v);
    return (u & 0x80000000u) ? ~u : (u | 0x80000000u);
}
__device__ __forceinline__ float fkey_inv(unsigned int k) {
    unsigned int u = (k & 0x80000000u) ? (k ^ 0x80000000u) : ~k;
    return __uint_as_float(u);
}

// h from already-loaded v + halo scalars. SINGLE implementation shared by both
// passes -> bit-identical fmax sequence -> identical survivor predicates.
__device__ __forceinline__ void hv_from_v(const float4& v, float hl, float hr,
                                          int lane, float4& h) {
    float lft = __shfl_up_sync(0xffffffffu, v.w, 1);
    float rgt = __shfl_down_sync(0xffffffffu, v.x, 1);
    if (lane == 0)  lft = hl;
    if (lane == 31) rgt = hr;
    h.x = fmaxf(fmaxf(lft, v.x), v.y);
    h.y = fmaxf(fmaxf(v.x, v.y), v.z);
    h.z = fmaxf(fmaxf(v.y, v.z), v.w);
    h.w = fmaxf(fmaxf(v.z, v.w), rgt);
}

// Load the 10 rows of chunk (c, y0, g) with all loads issued up-front (MLP=10),
// then produce h[10]. Shared by both passes.
__device__ __forceinline__ void load_chunk(const float* __restrict__ base,
                                           int y0, int g, int lane,
                                           float4* __restrict__ vr,
                                           float4* __restrict__ h) {
    float hl[10], hr[10];
    #pragma unroll
    for (int r = 0; r < 10; r++) {
        int yg = y0 - 1 + r;
        bool ok = (yg >= 0) && (yg < Hh);
        const float* row = base + (size_t)(ok ? yg : 0) * Wd;
        if (ok) {
            vr[r] = *(const float4*)(row + g * 128 + lane * 4);
            hl[r] = (lane == 0)  ? ((g > 0) ? row[g * 128 - 1]   : NEGF) : NEGF;
            hr[r] = (lane == 31) ? ((g < 3) ? row[g * 128 + 128] : NEGF) : NEGF;
        } else {
            vr[r].x = vr[r].y = vr[r].z = vr[r].w = NEGF;
            hl[r] = NEGF; hr[r] = NEGF;
        }
    }
    #pragma unroll
    for (int r = 0; r < 10; r++)
        hv_from_v(vr[r], hl[r], hr[r], lane, h[r]);
}

// ---- K1: per-warp chunk NMS (no tile staging) + smem histogram + chunk max ----
__global__ __launch_bounds__(256) void nms_hist_kernel(const float* __restrict__ hmap) {
    __shared__ unsigned int shist[NBINS];       // 4 KB only
    const int tid = threadIdx.x, lane = tid & 31, w = tid >> 5;
    for (int i = tid; i < NBINS; i += 256) shist[i] = 0u;
    __syncthreads();

    const unsigned int chunk = blockIdx.x * 8 + w;   // 20480 total
    const int g   = chunk & 3;
    const int ych = (chunk >> 2) & 63;
    const int c   = chunk >> 8;
    const int y0  = ych * 8;
    const float* __restrict__ base = hmap + (size_t)c * HW;

    float4 vr[10], h[10];
    load_chunk(base, y0, g, lane, vr, h);

    float smax = NEGF;
    #pragma unroll
    for (int r = 0; r < 8; r++) {
        float4 P = h[r], C = h[r + 1], N = h[r + 2], V = vr[r + 1];
        float m;
        m = fmaxf(fmaxf(P.x, C.x), N.x);
        if (m == V.x) { atomicAdd(&shist[fkey(V.x) >> BINSHIFT], 1u); smax = fmaxf(smax, V.x); }
        m = fmaxf(fmaxf(P.y, C.y), N.y);
        if (m == V.y) { atomicAdd(&shist[fkey(V.y) >> BINSHIFT], 1u); smax = fmaxf(smax, V.y); }
        m = fmaxf(fmaxf(P.z, C.z), N.z);
        if (m == V.z) { atomicAdd(&shist[fkey(V.z) >> BINSHIFT], 1u); smax = fmaxf(smax, V.z); }
        m = fmaxf(fmaxf(P.w, C.w), N.w);
        if (m == V.w) { atomicAdd(&shist[fkey(V.w) >> BINSHIFT], 1u); smax = fmaxf(smax, V.w); }
    }

    unsigned int km = fkey(smax);
    #pragma unroll
    for (int s = 16; s > 0; s >>= 1)
        km = max(km, __shfl_xor_sync(0xffffffffu, km, s));
    if (lane == 0) g_cmax[chunk] = km;

    __syncthreads();
    for (int i = tid; i < NBINS; i += 256) {
        unsigned int s = shist[i];
        if (s) atomicAdd(&g_hist[i], s);
    }
}

// ---- K2: threshold (parallel suffix scan, self-cleaning) ----
__global__ void thresh_kernel(int K) {
    __shared__ unsigned int s[NBINS];
    const int t = threadIdx.x;
    s[t] = g_hist[t];
    g_hist[t] = 0u;                       // clean for next graph replay
    if (t == 0) { g_nhot = 0u; g_ncand = 0u; g_thrkey = 0u; }
    __syncthreads();
    for (int d = 1; d < NBINS; d <<= 1) {
        unsigned int add = (t + d < NBINS) ? s[t + d] : 0u;
        __syncthreads();
        s[t] += add;
        __syncthreads();
    }
    if (s[t] >= (unsigned int)K && (t == NBINS - 1 || s[t + 1] < (unsigned int)K))
        g_thrkey = (unsigned int)t << BINSHIFT;
}

// ---- K2b: compact hot chunks (multi-block) ----
__global__ void compact_kernel() {
    const unsigned int thr = g_thrkey;
    unsigned int i = blockIdx.x * blockDim.x + threadIdx.x;
    if (i < NCHUNK && g_cmax[i] >= thr) {
        unsigned int p = atomicAdd(&g_nhot, 1u);
        if (p < HOT_CAP) g_hot[p] = i;
    }
}

// ---- K3: rescan hot chunks (one warp per chunk; 2048 warps) ----
__global__ __launch_bounds__(128) void cand_kernel(const float* __restrict__ hmap) {
    const unsigned int nhot = min(g_nhot, (unsigned int)HOT_CAP);
    const unsigned int thr = g_thrkey;
    const int lane = threadIdx.x & 31;
    const unsigned int warps = gridDim.x * (blockDim.x >> 5);
    for (unsigned int wi = blockIdx.x * (blockDim.x >> 5) + (threadIdx.x >> 5);
         wi < nhot; wi += warps) {
        const unsigned int chunk = g_hot[wi];
        const int g   = chunk & 3;
        const int ych = (chunk >> 2) & 63;
        const int c   = chunk >> 8;
        const int y0  = ych * 8;
        const float* __restrict__ base = hmap + (size_t)c * HW;

        float4 vr[10], h[10];
        load_chunk(base, y0, g, lane, vr, h);

        #pragma unroll
        for (int r = 0; r < 8; r++) {
            float4 P = h[r], C = h[r + 1], N = h[r + 2], V = vr[r + 1];
            float vv[4] = {V.x, V.y, V.z, V.w};
            float mm[4] = {fmaxf(fmaxf(P.x, C.x), N.x),
                           fmaxf(fmaxf(P.y, C.y), N.y),
                           fmaxf(fmaxf(P.z, C.z), N.z),
                           fmaxf(fmaxf(P.w, C.w), N.w)};
            #pragma unroll
            for (int e = 0; e < 4; e++) {
                if (mm[e] == vv[e]) {
                    unsigned int key = fkey(vv[e]);
                    if (key >= thr) {
                        unsigned int fl = (unsigned int)c * HW
                                        + (unsigned int)(y0 + r) * Wd
                                        + (unsigned int)(g * 128 + lane * 4 + e);
                        unsigned int p = atomicAdd(&g_ncand, 1u);
                        if (p < CAND_CAP)
                            g_cand[p] = ((unsigned long long)key << FLATBITS)
                                      | (unsigned long long)(FLATMASK - fl);
                    }
                }
            }
        }
    }
}

// ---- K4: exact rank (multi-block); gather + write output ----
__global__ __launch_bounds__(256) void output_kernel(const float* __restrict__ regs,
                              const float* __restrict__ wh,
                              const float* __restrict__ rot,
                              float* __restrict__ out, int K) {
    __shared__ unsigned long long sk[SH_CAND];
    unsigned int n = min(g_ncand, (unsigned int)CAND_CAP);
    bool sh = (n <= (unsigned int)SH_CAND);
    if (sh)
        for (unsigned int i = threadIdx.x; i < n; i += blockDim.x)
            sk[i] = g_cand[i];
    __syncthreads();

    for (unsigned int i = blockIdx.x * blockDim.x + threadIdx.x; i < n;
         i += gridDim.x * blockDim.x) {
        unsigned long long ki = sh ? sk[i] : g_cand[i];
        int rank = 0;
        for (unsigned int j = 0; j < n; j++) {
            unsigned long long kj = sh ? sk[j] : g_cand[j];
            rank += (kj > ki) ? 1 : 0;
        }
        if (rank < K) {
            unsigned int key  = (unsigned int)(ki >> FLATBITS);
            unsigned int flat = FLATMASK - (unsigned int)(ki & FLATMASK);
            unsigned int c    = flat / HW;
            unsigned int idx  = flat - c * HW;
            float yf = (float)(idx >> 9);
            float xf = (float)(idx & 511u);
            float vv = fkey_inv(key);
            float score = 1.0f / (1.0f + expf(-vv));
            float* o = out + (size_t)rank * 7;
            o[0] = xf + __ldg(&regs[idx]);
            o[1] = yf + __ldg(&regs[HW + idx]);
            o[2] = __ldg(&wh[idx]);
            o[3] = __ldg(&wh[HW + idx]);
            o[4] = __ldg(&rot[idx]);
            o[5] = score;
            o[6] = (float)c;
        }
    }
}

extern "C" void kernel_launch(void* const* d_in, const int* in_sizes, int n_in,
                              void* d_out, int out_size) {
    const float* hmap = (const float*)d_in[0];
    const float* regs = (const float*)d_in[1];
    const float* wh   = (const float*)d_in[2];
    const float* rot  = (const float*)d_in[3];
    float* out = (float*)d_out;
    int K = out_size / 7;  // B=1; [B,K,7]

    nms_hist_kernel<<<NCHUNK / 8, 256>>>(hmap);   // 2560 blocks
    thresh_kernel<<<1, NBINS>>>(K);
    compact_kernel<<<NCHUNK / 256, 256>>>();
    cand_kernel<<<512, 128>>>(hmap);
    output_kernel<<<32, 256>>>(regs, wh, rot, out, K);
}